// round 4
// baseline (speedup 1.0000x reference)
#include <cuda_runtime.h>
#include <cstdint>
#include <cstddef>

#define B_GR 256
#define N_PG 64
#define D_DIM 256
#define T_TOT 16384
#define E_TOT 524288
#define E_PG 2048
#define BOND_D 16
#define SLOPE 0.22916666666666666f

__device__ float g_eb1[134217728];
__device__ float g_eb2[134217728];
__device__ float g_y[4194304];
__device__ float g_z[4194304];
__device__ float g_xm1[4194304];
__device__ float g_xm2[4194304];
__device__ float g_r1[B_GR * 1280];
__device__ float g_r2[B_GR * 1280];
__device__ float g_o1[B_GR * D_DIM];
__device__ float g_o2[B_GR * D_DIM];
__device__ float g_fus[B_GR * 6];
__device__ int g_ptr1[T_TOT + 1];
__device__ int g_ptr2[T_TOT + 1];
__device__ int2 g_pack1[E_TOT];
__device__ int2 g_pack2[E_TOT];
__device__ int g_is64[2];

// ---- index dtype detection: int64 little-endian => odd words all zero ----
__global__ void detect_kernel(const unsigned* e1, const unsigned* e2) {
    if (threadIdx.x == 0) {
        int a = 1, b = 1;
        for (int i = 0; i < 512; i++) {
            if (e1[2 * i + 1]) a = 0;
            if (e2[2 * i + 1]) b = 0;
        }
        g_is64[0] = a;
        g_is64[1] = b;
    }
}

__device__ __forceinline__ int loadIdx(const void* p, int is64, long long i) {
    return is64 ? (int)((const long long*)p)[i] : ((const int*)p)[i];
}

// ---- per-graph CSR, dst-grouped, stable order (deterministic sums) ----
__global__ void build_csr(const void* __restrict__ eidx, int which,
                          int* __restrict__ ptr, int2* __restrict__ pack) {
    __shared__ int sl[E_PG], dl[E_PG], cnt[N_PG], base[N_PG];
    int g = blockIdx.x, t = threadIdx.x;
    int is64 = g_is64[which];
    if (t < N_PG) cnt[t] = 0;
    __syncthreads();
    for (int e = t; e < E_PG; e += blockDim.x) {
        long long ge = (long long)g * E_PG + e;
        sl[e] = loadIdx(eidx, is64, ge) - g * N_PG;
        int d = loadIdx(eidx, is64, (long long)E_TOT + ge) - g * N_PG;
        dl[e] = d;
        atomicAdd(&cnt[d], 1);
    }
    __syncthreads();
    if (t == 0) {
        int run = 0;
        for (int n = 0; n < N_PG; n++) {
            base[n] = run;
            ptr[g * N_PG + n] = g * E_PG + run;
            run += cnt[n];
        }
        if (g == 0) ptr[T_TOT] = E_TOT;
    }
    __syncthreads();
    if (t < N_PG) {
        int p = g * E_PG + base[t];
        for (int e = 0; e < E_PG; e++)
            if (dl[e] == t) { pack[p] = make_int2((g * E_PG + e) * D_DIM, sl[e] * D_DIM); p++; }
    }
}

// ---- eb[e][d] = bm[d] + sum_k ea[e][k] * We[k][d] ----
__global__ void edge_bias_kernel(const float* __restrict__ ea, const float* __restrict__ We,
                                 const float* __restrict__ bm, float* __restrict__ eb) {
    __shared__ float ea_s[256 * BOND_D];
    int d = threadIdx.x;
    int e0 = blockIdx.x * 256;
    float w[BOND_D];
#pragma unroll
    for (int k = 0; k < BOND_D; k++) w[k] = We[k * D_DIM + d];
    float bmd = bm[d];
    const float4* src = (const float4*)(ea + (size_t)e0 * BOND_D);
    float4* dst = (float4*)ea_s;
    for (int i = d; i < 256 * BOND_D / 4; i += 256) dst[i] = src[i];
    __syncthreads();
    for (int e = 0; e < 256; e++) {
        float v = bmd;
#pragma unroll
        for (int k = 0; k < BOND_D; k++) v += ea_s[e * BOND_D + k] * w[k];
        eb[(size_t)(e0 + e) * D_DIM + d] = v;
    }
}

// ---- SGEMM: C = act(A[M,K] @ B[K,N] + bias). BM=128 BN=64 BK=16, 256 thr, 8x4 ----
template <int ACT>
__global__ void sgemm_kernel(const float* __restrict__ A, const float* __restrict__ Bm,
                             const float* __restrict__ bias, float* __restrict__ C,
                             int M, int N, int K) {
    __shared__ float As[16 * 132];
    __shared__ float Bs[16 * 64];
    int tid = threadIdx.x;
    int col0 = blockIdx.x * 64, row0 = blockIdx.y * 128;
    int ar = tid >> 2, ac = (tid & 3) * 4;
    int br = tid >> 4, bc = (tid & 15) * 4;
    int ty8 = (tid >> 4) * 8, tx4 = (tid & 15) * 4;
    float acc[32];
#pragma unroll
    for (int i = 0; i < 32; i++) acc[i] = 0.f;
    for (int kt = 0; kt < K; kt += 16) {
        float4 av0 = *(const float4*)(A + (size_t)(row0 + ar) * K + kt + ac);
        float4 av1 = *(const float4*)(A + (size_t)(row0 + ar + 64) * K + kt + ac);
        float4 bv = *(const float4*)(Bm + (size_t)(kt + br) * N + col0 + bc);
        __syncthreads();
        As[(ac + 0) * 132 + ar] = av0.x; As[(ac + 1) * 132 + ar] = av0.y;
        As[(ac + 2) * 132 + ar] = av0.z; As[(ac + 3) * 132 + ar] = av0.w;
        As[(ac + 0) * 132 + ar + 64] = av1.x; As[(ac + 1) * 132 + ar + 64] = av1.y;
        As[(ac + 2) * 132 + ar + 64] = av1.z; As[(ac + 3) * 132 + ar + 64] = av1.w;
        *(float4*)&Bs[br * 64 + bc] = bv;
        __syncthreads();
#pragma unroll
        for (int k = 0; k < 16; k++) {
            float4 a0 = *(const float4*)&As[k * 132 + ty8];
            float4 a1 = *(const float4*)&As[k * 132 + ty8 + 4];
            float4 b = *(const float4*)&Bs[k * 64 + tx4];
            float av[8] = {a0.x, a0.y, a0.z, a0.w, a1.x, a1.y, a1.z, a1.w};
            float bb[4] = {b.x, b.y, b.z, b.w};
#pragma unroll
            for (int i = 0; i < 8; i++)
#pragma unroll
                for (int j = 0; j < 4; j++) acc[i * 4 + j] += av[i] * bb[j];
        }
    }
    float4 bias4 = make_float4(0.f, 0.f, 0.f, 0.f);
    if (bias) bias4 = *(const float4*)(bias + col0 + tx4);
#pragma unroll
    for (int i = 0; i < 8; i++) {
        float4 v;
        v.x = acc[i * 4 + 0] + bias4.x; v.y = acc[i * 4 + 1] + bias4.y;
        v.z = acc[i * 4 + 2] + bias4.z; v.w = acc[i * 4 + 3] + bias4.w;
        if (ACT == 2) {
            v.x = v.x >= 0.f ? v.x : SLOPE * v.x; v.y = v.y >= 0.f ? v.y : SLOPE * v.y;
            v.z = v.z >= 0.f ? v.z : SLOPE * v.z; v.w = v.w >= 0.f ? v.w : SLOPE * v.w;
        }
        *(float4*)(C + (size_t)(row0 + ty8 + i) * N + col0 + tx4) = v;
    }
}

// ---- conv: xo = relu(z + segsum(relu(y[src]+eb)) + bs), one CTA/graph ----
__global__ void conv_kernel(const float* __restrict__ y, const float* __restrict__ z,
                            const float* __restrict__ eb, const int* __restrict__ ptr,
                            const int2* __restrict__ pack, const float* __restrict__ bs,
                            float* __restrict__ xo) {
    extern __shared__ float ys[];
    int g = blockIdx.x, t = threadIdx.x;
    const float* yg = y + (size_t)g * N_PG * D_DIM;
    for (int i = t; i < N_PG * D_DIM; i += 256) ys[i] = yg[i];
    __syncthreads();
    int q = t >> 6, dd = (t & 63) * 4;
    float4 bsv = *(const float4*)(bs + dd);
    for (int n = q; n < N_PG; n += 4) {
        int p0 = ptr[g * N_PG + n], p1 = ptr[g * N_PG + n + 1];
        float ax = 0.f, ay = 0.f, az = 0.f, aw = 0.f;
        for (int j = p0; j < p1; j++) {
            int2 pr = pack[j];
            float4 yv = *(const float4*)(ys + pr.y + dd);
            float4 ev = *(const float4*)(eb + (size_t)pr.x + dd);
            ax += fmaxf(yv.x + ev.x, 0.f); ay += fmaxf(yv.y + ev.y, 0.f);
            az += fmaxf(yv.z + ev.z, 0.f); aw += fmaxf(yv.w + ev.w, 0.f);
        }
        size_t o = (size_t)(g * N_PG + n) * D_DIM + dd;
        float4 zv = *(const float4*)(z + o);
        float4 r;
        r.x = fmaxf(zv.x + ax + bsv.x, 0.f); r.y = fmaxf(zv.y + ay + bsv.y, 0.f);
        r.z = fmaxf(zv.z + az + bsv.z, 0.f); r.w = fmaxf(zv.w + aw + bsv.w, 0.f);
        *(float4*)(xo + o) = r;
    }
}

// ---- dot_pool: per-graph 64x64 cross dots, max & mean ----
__global__ void dotpool_kernel(const float* __restrict__ x1, const float* __restrict__ x2,
                               float* __restrict__ fus, int s) {
    extern __shared__ float sm[];
    float* a = sm;
    float* b = sm + 256 * 65;
    __shared__ float rm[256], rs[256];
    int g = blockIdx.x, t = threadIdx.x;
    const float* p1 = x1 + (size_t)g * N_PG * D_DIM;
    const float* p2 = x2 + (size_t)g * N_PG * D_DIM;
    for (int i = t; i < N_PG * D_DIM; i += 256) {
        int n = i >> 8, d = i & 255;
        a[d * 65 + n] = p1[i];
        b[d * 65 + n] = p2[i];
    }
    __syncthreads();
    int ti = t & 15, tj = t >> 4;
    float acc[16];
#pragma unroll
    for (int i = 0; i < 16; i++) acc[i] = 0.f;
    for (int d = 0; d < 256; d++) {
        float av[4], bv[4];
#pragma unroll
        for (int u = 0; u < 4; u++) { av[u] = a[d * 65 + ti + 16 * u]; bv[u] = b[d * 65 + tj + 16 * u]; }
#pragma unroll
        for (int i = 0; i < 4; i++)
#pragma unroll
            for (int j = 0; j < 4; j++) acc[i * 4 + j] += av[i] * bv[j];
    }
    float lmax = -3.4e38f, ls = 0.f;
#pragma unroll
    for (int i = 0; i < 16; i++) { lmax = fmaxf(lmax, acc[i]); ls += acc[i]; }
    rm[t] = lmax; rs[t] = ls;
    __syncthreads();
    for (int o = 128; o > 0; o >>= 1) {
        if (t < o) { rm[t] = fmaxf(rm[t], rm[t + o]); rs[t] += rs[t + o]; }
        __syncthreads();
    }
    if (t == 0) { fus[g * 6 + 2 * s] = rm[0]; fus[g * 6 + 2 * s + 1] = rs[0] / 4096.f; }
}

// ---- readout: [mean, sum, top-3 rows by last feature] -> [B,1280] ----
__global__ void readout_kernel(const float* __restrict__ x, float* __restrict__ r) {
    __shared__ int ord[3];
    int g = blockIdx.x, t = threadIdx.x;
    const float* xg = x + (size_t)g * N_PG * D_DIM;
    float s = 0.f;
    for (int n = 0; n < N_PG; n++) s += xg[n * D_DIM + t];
    r[g * 1280 + t] = s / 64.f;
    r[g * 1280 + 256 + t] = s;
    if (t < 32) {
        float v0 = xg[t * D_DIM + 255], v1 = xg[(t + 32) * D_DIM + 255];
        int i0 = t, i1 = t + 32;
        for (int k = 0; k < 3; k++) {
            float cv; int bi;
            if (v0 > v1 || (v0 == v1 && i0 < i1)) { cv = v0; bi = i0; } else { cv = v1; bi = i1; }
            for (int o = 16; o > 0; o >>= 1) {
                float ov = __shfl_down_sync(0xffffffffu, cv, o);
                int oi = __shfl_down_sync(0xffffffffu, bi, o);
                if (ov > cv || (ov == cv && oi < bi)) { cv = ov; bi = oi; }
            }
            bi = __shfl_sync(0xffffffffu, bi, 0);
            if (t == 0) ord[k] = bi;
            if (bi == i0) v0 = -3.4e38f;
            if (bi == i1) v1 = -3.4e38f;
        }
    }
    __syncthreads();
    for (int k = 0; k < 3; k++) r[g * 1280 + 512 + k * 256 + t] = xg[ord[k] * D_DIM + t];
}

// ---- head: cat[518] @ Wo1 + bo1 -> @ Wo2 + bo2 -> [B,2] ----
__global__ void head_kernel(const float* __restrict__ o1, const float* __restrict__ o2,
                            const float* __restrict__ fus, const float* __restrict__ Wo1,
                            const float* __restrict__ bo1, const float* __restrict__ Wo2,
                            const float* __restrict__ bo2, float* __restrict__ out) {
    __shared__ float cat[518];
    __shared__ float r0[256], r1a[256];
    int g = blockIdx.x, t = threadIdx.x;
    cat[t] = o1[g * 256 + t];
    cat[256 + t] = o2[g * 256 + t];
    if (t < 6) cat[512 + t] = fus[g * 6 + t];
    __syncthreads();
    float h = bo1[t];
    for (int k = 0; k < 518; k++) h += cat[k] * Wo1[k * 256 + t];
    r0[t] = h * Wo2[t * 2];
    r1a[t] = h * Wo2[t * 2 + 1];
    __syncthreads();
    for (int o = 128; o > 0; o >>= 1) {
        if (t < o) { r0[t] += r0[t + o]; r1a[t] += r1a[t + o]; }
        __syncthreads();
    }
    if (t == 0) { out[g * 2] = r0[0] + bo2[0]; out[g * 2 + 1] = r1a[0] + bo2[1]; }
}

extern "C" void kernel_launch(void* const* d_in, const int* in_sizes, int n_in,
                              void* d_out, int out_size) {
    const float* x1 = (const float*)d_in[0];
    const void* ei1 = d_in[1];
    const float* ea1 = (const float*)d_in[2];
    const float* x2 = (const float*)d_in[4];
    const void* ei2 = d_in[5];
    const float* ea2 = (const float*)d_in[6];
    const float* W0_1 = (const float*)d_in[8];  const float* b0_1 = (const float*)d_in[9];
    const float* W0_2 = (const float*)d_in[10]; const float* b0_2 = (const float*)d_in[11];
    const float* Wn1 = (const float*)d_in[12];  const float* We1 = (const float*)d_in[13];
    const float* bm1 = (const float*)d_in[14];  const float* Ws1 = (const float*)d_in[15];
    const float* bs1 = (const float*)d_in[16];
    const float* Wn2 = (const float*)d_in[17];  const float* We2 = (const float*)d_in[18];
    const float* bm2 = (const float*)d_in[19];  const float* Ws2 = (const float*)d_in[20];
    const float* bs2 = (const float*)d_in[21];
    const float* Wf1 = (const float*)d_in[22];  const float* bf1 = (const float*)d_in[23];
    const float* Wf2 = (const float*)d_in[24];  const float* bf2 = (const float*)d_in[25];
    const float* Wo1 = (const float*)d_in[26];  const float* bo1 = (const float*)d_in[27];
    const float* Wo2 = (const float*)d_in[28];  const float* bo2 = (const float*)d_in[29];
    float* out = (float*)d_out;

    void* p;
    cudaGetSymbolAddress(&p, g_eb1);  float* eb1 = (float*)p;
    cudaGetSymbolAddress(&p, g_eb2);  float* eb2 = (float*)p;
    cudaGetSymbolAddress(&p, g_y);    float* yb = (float*)p;
    cudaGetSymbolAddress(&p, g_z);    float* zb = (float*)p;
    cudaGetSymbolAddress(&p, g_xm1);  float* xm1 = (float*)p;
    cudaGetSymbolAddress(&p, g_xm2);  float* xm2 = (float*)p;
    cudaGetSymbolAddress(&p, g_r1);   float* r1 = (float*)p;
    cudaGetSymbolAddress(&p, g_r2);   float* r2 = (float*)p;
    cudaGetSymbolAddress(&p, g_o1);   float* o1 = (float*)p;
    cudaGetSymbolAddress(&p, g_o2);   float* o2 = (float*)p;
    cudaGetSymbolAddress(&p, g_fus);  float* fus = (float*)p;
    cudaGetSymbolAddress(&p, g_ptr1); int* ptr1 = (int*)p;
    cudaGetSymbolAddress(&p, g_ptr2); int* ptr2 = (int*)p;
    cudaGetSymbolAddress(&p, g_pack1); int2* pack1 = (int2*)p;
    cudaGetSymbolAddress(&p, g_pack2); int2* pack2 = (int2*)p;

    cudaFuncSetAttribute(conv_kernel, cudaFuncAttributeMaxDynamicSharedMemorySize, 65536);
    cudaFuncSetAttribute(dotpool_kernel, cudaFuncAttributeMaxDynamicSharedMemorySize, 2 * 65 * 256 * 4);

    detect_kernel<<<1, 32>>>((const unsigned*)ei1, (const unsigned*)ei2);
    build_csr<<<B_GR, 256>>>(ei1, 0, ptr1, pack1);
    build_csr<<<B_GR, 256>>>(ei2, 1, ptr2, pack2);
    edge_bias_kernel<<<E_TOT / 256, 256>>>(ea1, We1, bm1, eb1);
    edge_bias_kernel<<<E_TOT / 256, 256>>>(ea2, We2, bm2, eb2);

    dim3 gT(4, 128);
    sgemm_kernel<2><<<gT, 256>>>(x1, W0_1, b0_1, xm1, T_TOT, 256, 128);
    sgemm_kernel<2><<<gT, 256>>>(x2, W0_2, b0_2, xm2, T_TOT, 256, 128);

    for (int s = 0; s < 3; s++) {
        sgemm_kernel<0><<<gT, 256>>>(xm1, Wn1, nullptr, yb, T_TOT, 256, 256);
        sgemm_kernel<0><<<gT, 256>>>(xm1, Ws1, nullptr, zb, T_TOT, 256, 256);
        conv_kernel<<<B_GR, 256, 65536>>>(yb, zb, eb1, ptr1, pack1, bs1, xm1);
        sgemm_kernel<0><<<gT, 256>>>(xm2, Wn2, nullptr, yb, T_TOT, 256, 256);
        sgemm_kernel<0><<<gT, 256>>>(xm2, Ws2, nullptr, zb, T_TOT, 256, 256);
        conv_kernel<<<B_GR, 256, 65536>>>(yb, zb, eb2, ptr2, pack2, bs2, xm2);
        dotpool_kernel<<<B_GR, 256, 2 * 65 * 256 * 4>>>(xm1, xm2, fus, s);
    }

    readout_kernel<<<B_GR, 256>>>(xm1, r1);
    readout_kernel<<<B_GR, 256>>>(xm2, r2);
    dim3 gF(4, 2);
    sgemm_kernel<0><<<gF, 256>>>(r1, Wf1, bf1, o1, 256, 256, 1280);
    sgemm_kernel<0><<<gF, 256>>>(r2, Wf2, bf2, o2, 256, 256, 1280);
    head_kernel<<<B_GR, 256>>>(o1, o2, fus, Wo1, bo1, Wo2, bo2, out);
}

// round 5
// speedup vs baseline: 1.0300x; 1.0300x over previous
#include <cuda_runtime.h>
#include <cuda_fp16.h>
#include <cstdint>
#include <cstddef>

#define B_GR 256
#define N_PG 64
#define D_DIM 256
#define T_TOT 16384
#define E_TOT 524288
#define E_PG 2048
#define BOND_D 16
#define SLOPE 0.22916666666666666f

__device__ __half g_eb1[134217728];   // 256 MB fp16 edge bias mol1
__device__ __half g_eb2[134217728];   // 256 MB fp16 edge bias mol2
__device__ float g_y[4194304];
__device__ float g_z[4194304];
__device__ float g_xm1[4194304];
__device__ float g_xm2[4194304];
__device__ float g_r1[B_GR * 1280];
__device__ float g_r2[B_GR * 1280];
__device__ float g_o1[B_GR * D_DIM];
__device__ float g_o2[B_GR * D_DIM];
__device__ float g_fus[B_GR * 6];
__device__ int g_ptr1[T_TOT + 1];
__device__ int g_ptr2[T_TOT + 1];
__device__ int2 g_pack1[E_TOT];
__device__ int2 g_pack2[E_TOT];
__device__ int g_is64[2];

// ---- index dtype detection (parallel): int64 LE => odd 32-bit words all zero ----
__global__ void detect_kernel(const unsigned* e1, const unsigned* e2) {
    __shared__ int ok[2];
    int t = threadIdx.x;
    if (t < 2) ok[t] = 1;
    __syncthreads();
    if (e1[2 * t + 1]) ok[0] = 0;   // benign race: all writers store 0
    if (e2[2 * t + 1]) ok[1] = 0;
    __syncthreads();
    if (t < 2) g_is64[t] = ok[t];
}

__device__ __forceinline__ int loadIdx(const void* p, int is64, long long i) {
    return is64 ? (int)((const long long*)p)[i] : ((const int*)p)[i];
}

// ---- per-graph CSR, dst-grouped, stable order (deterministic sums) ----
__global__ void build_csr(const void* __restrict__ eidx, int which,
                          int* __restrict__ ptr, int2* __restrict__ pack) {
    __shared__ int sl[E_PG], dl[E_PG], cnt[N_PG], base[N_PG];
    int g = blockIdx.x, t = threadIdx.x;
    int is64 = g_is64[which];
    if (t < N_PG) cnt[t] = 0;
    __syncthreads();
    for (int e = t; e < E_PG; e += blockDim.x) {
        long long ge = (long long)g * E_PG + e;
        sl[e] = loadIdx(eidx, is64, ge) - g * N_PG;
        int d = loadIdx(eidx, is64, (long long)E_TOT + ge) - g * N_PG;
        dl[e] = d;
        atomicAdd(&cnt[d], 1);
    }
    __syncthreads();
    if (t == 0) {
        int run = 0;
        for (int n = 0; n < N_PG; n++) {
            base[n] = run;
            ptr[g * N_PG + n] = g * E_PG + run;
            run += cnt[n];
        }
        if (g == 0) ptr[T_TOT] = E_TOT;
    }
    __syncthreads();
    if (t < N_PG) {
        int p = g * E_PG + base[t];
        for (int e = 0; e < E_PG; e++)
            if (dl[e] == t) { pack[p] = make_int2((g * E_PG + e) * D_DIM, sl[e] * D_DIM); p++; }
    }
}

// ---- eb[e][d] = fp16( bm[d] + sum_k ea[e][k] * We[k][d] ) ----
__global__ void edge_bias_kernel(const float* __restrict__ ea, const float* __restrict__ We,
                                 const float* __restrict__ bm, __half* __restrict__ eb) {
    __shared__ float ea_s[256 * BOND_D];
    int d = threadIdx.x;
    int e0 = blockIdx.x * 256;
    float w[BOND_D];
#pragma unroll
    for (int k = 0; k < BOND_D; k++) w[k] = We[k * D_DIM + d];
    float bmd = bm[d];
    const float4* src = (const float4*)(ea + (size_t)e0 * BOND_D);
    float4* dst = (float4*)ea_s;
    for (int i = d; i < 256 * BOND_D / 4; i += 256) dst[i] = src[i];
    __syncthreads();
    for (int e = 0; e < 256; e++) {
        float v = bmd;
#pragma unroll
        for (int k = 0; k < BOND_D; k++) v += ea_s[e * BOND_D + k] * w[k];
        eb[(size_t)(e0 + e) * D_DIM + d] = __float2half_rn(v);
    }
}

// ---- SGEMM: C = act(A[M,K] @ B[K,N] + bias). 128x128x8, 256 thr, 8x8, dbuf ----
template <int ACT>
__global__ void sgemm128(const float* __restrict__ A, const float* __restrict__ Bm,
                         const float* __restrict__ bias, float* __restrict__ C,
                         int M, int N, int K) {
    __shared__ float As[2][8 * 132];
    __shared__ float Bs[2][8 * 128];
    int tid = threadIdx.x;
    int row0 = blockIdx.y * 128, col0 = blockIdx.x * 128;
    int arow = tid >> 1, akc = (tid & 1) * 4;
    int bkr = tid >> 5, bcol = (tid & 31) * 4;
    int tx4 = (tid & 15) * 4, ty4 = (tid >> 4) * 4;
    const float* Aptr = A + (size_t)(row0 + arow) * K + akc;
    const float* Bptr = Bm + (size_t)bkr * N + col0 + bcol;
    float acc[8][8];
#pragma unroll
    for (int i = 0; i < 8; i++)
#pragma unroll
        for (int j = 0; j < 8; j++) acc[i][j] = 0.f;
    float4 aR = *(const float4*)Aptr;
    float4 bR = *(const float4*)Bptr;
    As[0][(akc + 0) * 132 + arow] = aR.x;
    As[0][(akc + 1) * 132 + arow] = aR.y;
    As[0][(akc + 2) * 132 + arow] = aR.z;
    As[0][(akc + 3) * 132 + arow] = aR.w;
    *(float4*)&Bs[0][bkr * 128 + bcol] = bR;
    __syncthreads();
    int NT = K >> 3;
    int buf = 0;
    for (int kt = 0; kt < NT; kt++) {
        if (kt < NT - 1) {
            aR = *(const float4*)(Aptr + (kt + 1) * 8);
            bR = *(const float4*)(Bptr + (size_t)(kt + 1) * 8 * N);
        }
        const float* as = As[buf];
        const float* bs_ = Bs[buf];
#pragma unroll
        for (int k = 0; k < 8; k++) {
            float4 a0 = *(const float4*)&as[k * 132 + ty4];
            float4 a1 = *(const float4*)&as[k * 132 + ty4 + 64];
            float4 b0 = *(const float4*)&bs_[k * 128 + tx4];
            float4 b1 = *(const float4*)&bs_[k * 128 + tx4 + 64];
            float av[8] = {a0.x, a0.y, a0.z, a0.w, a1.x, a1.y, a1.z, a1.w};
            float bv[8] = {b0.x, b0.y, b0.z, b0.w, b1.x, b1.y, b1.z, b1.w};
#pragma unroll
            for (int i = 0; i < 8; i++)
#pragma unroll
                for (int j = 0; j < 8; j++) acc[i][j] += av[i] * bv[j];
        }
        if (kt < NT - 1) {
            buf ^= 1;
            As[buf][(akc + 0) * 132 + arow] = aR.x;
            As[buf][(akc + 1) * 132 + arow] = aR.y;
            As[buf][(akc + 2) * 132 + arow] = aR.z;
            As[buf][(akc + 3) * 132 + arow] = aR.w;
            *(float4*)&Bs[buf][bkr * 128 + bcol] = bR;
            __syncthreads();
        }
    }
    float4 bias0 = make_float4(0.f, 0.f, 0.f, 0.f), bias1 = bias0;
    if (bias) {
        bias0 = *(const float4*)(bias + col0 + tx4);
        bias1 = *(const float4*)(bias + col0 + tx4 + 64);
    }
    float bb[8] = {bias0.x, bias0.y, bias0.z, bias0.w, bias1.x, bias1.y, bias1.z, bias1.w};
#pragma unroll
    for (int i = 0; i < 8; i++) {
        int row = row0 + ((i < 4) ? (ty4 + i) : (ty4 + 60 + i));
        float v[8];
#pragma unroll
        for (int j = 0; j < 8; j++) {
            v[j] = acc[i][j] + bb[j];
            if (ACT == 2) v[j] = v[j] >= 0.f ? v[j] : SLOPE * v[j];
        }
        *(float4*)(C + (size_t)row * N + col0 + tx4) = make_float4(v[0], v[1], v[2], v[3]);
        *(float4*)(C + (size_t)row * N + col0 + tx4 + 64) = make_float4(v[4], v[5], v[6], v[7]);
    }
}

// ---- conv: xo = relu(z + segsum(relu(y[src]+eb)) + bs), one CTA/graph ----
__global__ void conv_kernel(const float* __restrict__ y, const float* __restrict__ z,
                            const __half* __restrict__ eb, const int* __restrict__ ptr,
                            const int2* __restrict__ pack, const float* __restrict__ bs,
                            float* __restrict__ xo) {
    extern __shared__ float ys[];
    int g = blockIdx.x, t = threadIdx.x;
    const float* yg = y + (size_t)g * N_PG * D_DIM;
    for (int i = t; i < N_PG * D_DIM; i += 256) ys[i] = yg[i];
    __syncthreads();
    int q = t >> 6, dd = (t & 63) * 4;
    float4 bsv = *(const float4*)(bs + dd);
    for (int n = q; n < N_PG; n += 4) {
        int p0 = ptr[g * N_PG + n], p1 = ptr[g * N_PG + n + 1];
        float ax = 0.f, ay = 0.f, az = 0.f, aw = 0.f;
        for (int j = p0; j < p1; j++) {
            int2 pr = pack[j];
            float4 yv = *(const float4*)(ys + pr.y + dd);
            uint2 raw = *(const uint2*)(eb + (size_t)pr.x + dd);
            float2 e0 = __half22float2(*(__half2*)&raw.x);
            float2 e1 = __half22float2(*(__half2*)&raw.y);
            ax += fmaxf(yv.x + e0.x, 0.f); ay += fmaxf(yv.y + e0.y, 0.f);
            az += fmaxf(yv.z + e1.x, 0.f); aw += fmaxf(yv.w + e1.y, 0.f);
        }
        size_t o = (size_t)(g * N_PG + n) * D_DIM + dd;
        float4 zv = *(const float4*)(z + o);
        float4 r;
        r.x = fmaxf(zv.x + ax + bsv.x, 0.f); r.y = fmaxf(zv.y + ay + bsv.y, 0.f);
        r.z = fmaxf(zv.z + az + bsv.z, 0.f); r.w = fmaxf(zv.w + aw + bsv.w, 0.f);
        *(float4*)(xo + o) = r;
    }
}

// ---- dot_pool: per-graph 64x64 cross dots, max & mean ----
__global__ void dotpool_kernel(const float* __restrict__ x1, const float* __restrict__ x2,
                               float* __restrict__ fus, int s) {
    extern __shared__ float sm[];
    float* a = sm;
    float* b = sm + 256 * 65;
    __shared__ float rm[256], rs[256];
    int g = blockIdx.x, t = threadIdx.x;
    const float* p1 = x1 + (size_t)g * N_PG * D_DIM;
    const float* p2 = x2 + (size_t)g * N_PG * D_DIM;
    for (int i = t; i < N_PG * D_DIM; i += 256) {
        int n = i >> 8, d = i & 255;
        a[d * 65 + n] = p1[i];
        b[d * 65 + n] = p2[i];
    }
    __syncthreads();
    int ti = t & 15, tj = t >> 4;
    float acc[16];
#pragma unroll
    for (int i = 0; i < 16; i++) acc[i] = 0.f;
    for (int d = 0; d < 256; d++) {
        float av[4], bv[4];
#pragma unroll
        for (int u = 0; u < 4; u++) { av[u] = a[d * 65 + ti + 16 * u]; bv[u] = b[d * 65 + tj + 16 * u]; }
#pragma unroll
        for (int i = 0; i < 4; i++)
#pragma unroll
            for (int j = 0; j < 4; j++) acc[i * 4 + j] += av[i] * bv[j];
    }
    float lmax = -3.4e38f, ls = 0.f;
#pragma unroll
    for (int i = 0; i < 16; i++) { lmax = fmaxf(lmax, acc[i]); ls += acc[i]; }
    rm[t] = lmax; rs[t] = ls;
    __syncthreads();
    for (int o = 128; o > 0; o >>= 1) {
        if (t < o) { rm[t] = fmaxf(rm[t], rm[t + o]); rs[t] += rs[t + o]; }
        __syncthreads();
    }
    if (t == 0) { fus[g * 6 + 2 * s] = rm[0]; fus[g * 6 + 2 * s + 1] = rs[0] / 4096.f; }
}

// ---- readout: [mean, sum, top-3 rows by last feature] -> [B,1280] ----
__global__ void readout_kernel(const float* __restrict__ x, float* __restrict__ r) {
    __shared__ int ord[3];
    int g = blockIdx.x, t = threadIdx.x;
    const float* xg = x + (size_t)g * N_PG * D_DIM;
    float s = 0.f;
    for (int n = 0; n < N_PG; n++) s += xg[n * D_DIM + t];
    r[g * 1280 + t] = s / 64.f;
    r[g * 1280 + 256 + t] = s;
    if (t < 32) {
        float v0 = xg[t * D_DIM + 255], v1 = xg[(t + 32) * D_DIM + 255];
        int i0 = t, i1 = t + 32;
        for (int k = 0; k < 3; k++) {
            float cv; int bi;
            if (v0 > v1 || (v0 == v1 && i0 < i1)) { cv = v0; bi = i0; } else { cv = v1; bi = i1; }
            for (int o = 16; o > 0; o >>= 1) {
                float ov = __shfl_down_sync(0xffffffffu, cv, o);
                int oi = __shfl_down_sync(0xffffffffu, bi, o);
                if (ov > cv || (ov == cv && oi < bi)) { cv = ov; bi = oi; }
            }
            bi = __shfl_sync(0xffffffffu, bi, 0);
            if (t == 0) ord[k] = bi;
            if (bi == i0) v0 = -3.4e38f;
            if (bi == i1) v1 = -3.4e38f;
        }
    }
    __syncthreads();
    for (int k = 0; k < 3; k++) r[g * 1280 + 512 + k * 256 + t] = xg[ord[k] * D_DIM + t];
}

// ---- head: cat[518] @ Wo1 + bo1 -> @ Wo2 + bo2 -> [B,2] ----
__global__ void head_kernel(const float* __restrict__ o1, const float* __restrict__ o2,
                            const float* __restrict__ fus, const float* __restrict__ Wo1,
                            const float* __restrict__ bo1, const float* __restrict__ Wo2,
                            const float* __restrict__ bo2, float* __restrict__ out) {
    __shared__ float cat[518];
    __shared__ float r0[256], r1a[256];
    int g = blockIdx.x, t = threadIdx.x;
    cat[t] = o1[g * 256 + t];
    cat[256 + t] = o2[g * 256 + t];
    if (t < 6) cat[512 + t] = fus[g * 6 + t];
    __syncthreads();
    float h = bo1[t];
    for (int k = 0; k < 518; k++) h += cat[k] * Wo1[k * 256 + t];
    r0[t] = h * Wo2[t * 2];
    r1a[t] = h * Wo2[t * 2 + 1];
    __syncthreads();
    for (int o = 128; o > 0; o >>= 1) {
        if (t < o) { r0[t] += r0[t + o]; r1a[t] += r1a[t + o]; }
        __syncthreads();
    }
    if (t == 0) { out[g * 2] = r0[0] + bo2[0]; out[g * 2 + 1] = r1a[0] + bo2[1]; }
}

extern "C" void kernel_launch(void* const* d_in, const int* in_sizes, int n_in,
                              void* d_out, int out_size) {
    const float* x1 = (const float*)d_in[0];
    const void* ei1 = d_in[1];
    const float* ea1 = (const float*)d_in[2];
    const float* x2 = (const float*)d_in[4];
    const void* ei2 = d_in[5];
    const float* ea2 = (const float*)d_in[6];
    const float* W0_1 = (const float*)d_in[8];  const float* b0_1 = (const float*)d_in[9];
    const float* W0_2 = (const float*)d_in[10]; const float* b0_2 = (const float*)d_in[11];
    const float* Wn1 = (const float*)d_in[12];  const float* We1 = (const float*)d_in[13];
    const float* bm1 = (const float*)d_in[14];  const float* Ws1 = (const float*)d_in[15];
    const float* bs1 = (const float*)d_in[16];
    const float* Wn2 = (const float*)d_in[17];  const float* We2 = (const float*)d_in[18];
    const float* bm2 = (const float*)d_in[19];  const float* Ws2 = (const float*)d_in[20];
    const float* bs2 = (const float*)d_in[21];
    const float* Wf1 = (const float*)d_in[22];  const float* bf1 = (const float*)d_in[23];
    const float* Wf2 = (const float*)d_in[24];  const float* bf2 = (const float*)d_in[25];
    const float* Wo1 = (const float*)d_in[26];  const float* bo1 = (const float*)d_in[27];
    const float* Wo2 = (const float*)d_in[28];  const float* bo2 = (const float*)d_in[29];
    float* out = (float*)d_out;

    void* p;
    cudaGetSymbolAddress(&p, g_eb1);  __half* eb1 = (__half*)p;
    cudaGetSymbolAddress(&p, g_eb2);  __half* eb2 = (__half*)p;
    cudaGetSymbolAddress(&p, g_y);    float* yb = (float*)p;
    cudaGetSymbolAddress(&p, g_z);    float* zb = (float*)p;
    cudaGetSymbolAddress(&p, g_xm1);  float* xm1 = (float*)p;
    cudaGetSymbolAddress(&p, g_xm2);  float* xm2 = (float*)p;
    cudaGetSymbolAddress(&p, g_r1);   float* r1 = (float*)p;
    cudaGetSymbolAddress(&p, g_r2);   float* r2 = (float*)p;
    cudaGetSymbolAddress(&p, g_o1);   float* o1 = (float*)p;
    cudaGetSymbolAddress(&p, g_o2);   float* o2 = (float*)p;
    cudaGetSymbolAddress(&p, g_fus);  float* fus = (float*)p;
    cudaGetSymbolAddress(&p, g_ptr1); int* ptr1 = (int*)p;
    cudaGetSymbolAddress(&p, g_ptr2); int* ptr2 = (int*)p;
    cudaGetSymbolAddress(&p, g_pack1); int2* pack1 = (int2*)p;
    cudaGetSymbolAddress(&p, g_pack2); int2* pack2 = (int2*)p;

    cudaFuncSetAttribute(conv_kernel, cudaFuncAttributeMaxDynamicSharedMemorySize, 65536);
    cudaFuncSetAttribute(dotpool_kernel, cudaFuncAttributeMaxDynamicSharedMemorySize, 2 * 65 * 256 * 4);

    detect_kernel<<<1, 512>>>((const unsigned*)ei1, (const unsigned*)ei2);
    build_csr<<<B_GR, 256>>>(ei1, 0, ptr1, pack1);
    build_csr<<<B_GR, 256>>>(ei2, 1, ptr2, pack2);
    edge_bias_kernel<<<E_TOT / 256, 256>>>(ea1, We1, bm1, eb1);
    edge_bias_kernel<<<E_TOT / 256, 256>>>(ea2, We2, bm2, eb2);

    dim3 gT(2, 128);   // N=256, M=16384
    sgemm128<2><<<gT, 256>>>(x1, W0_1, b0_1, xm1, T_TOT, 256, 128);
    sgemm128<2><<<gT, 256>>>(x2, W0_2, b0_2, xm2, T_TOT, 256, 128);

    for (int s = 0; s < 3; s++) {
        sgemm128<0><<<gT, 256>>>(xm1, Wn1, nullptr, yb, T_TOT, 256, 256);
        sgemm128<0><<<gT, 256>>>(xm1, Ws1, nullptr, zb, T_TOT, 256, 256);
        conv_kernel<<<B_GR, 256, 65536>>>(yb, zb, eb1, ptr1, pack1, bs1, xm1);
        sgemm128<0><<<gT, 256>>>(xm2, Wn2, nullptr, yb, T_TOT, 256, 256);
        sgemm128<0><<<gT, 256>>>(xm2, Ws2, nullptr, zb, T_TOT, 256, 256);
        conv_kernel<<<B_GR, 256, 65536>>>(yb, zb, eb2, ptr2, pack2, bs2, xm2);
        dotpool_kernel<<<B_GR, 256, 2 * 65 * 256 * 4>>>(xm1, xm2, fus, s);
    }

    readout_kernel<<<B_GR, 256>>>(xm1, r1);
    readout_kernel<<<B_GR, 256>>>(xm2, r2);
    dim3 gF(2, 2);     // N=256, M=256
    sgemm128<0><<<gF, 256>>>(r1, Wf1, bf1, o1, 256, 256, 1280);
    sgemm128<0><<<gF, 256>>>(r2, Wf2, bf2, o2, 256, 256, 1280);
    head_kernel<<<B_GR, 256>>>(o1, o2, fus, Wo1, bo1, Wo2, bo2, out);
}

// round 6
// speedup vs baseline: 1.2651x; 1.2283x over previous
#include <cuda_runtime.h>
#include <cuda_fp16.h>
#include <cstdint>
#include <cstddef>

#define B_GR 256
#define N_PG 64
#define D_DIM 256
#define T_TOT 16384
#define E_TOT 524288
#define E_PG 2048
#define BOND_D 16
#define SLOPE 0.22916666666666666f

__device__ __half g_eb1[134217728];   // 256 MB fp16 edge bias mol1
__device__ __half g_eb2[134217728];   // 256 MB fp16 edge bias mol2
__device__ float g_y[4194304];
__device__ float g_z[4194304];
__device__ float g_xm1[4194304];
__device__ float g_xm2[4194304];
__device__ float g_r1[B_GR * 1280];
__device__ float g_r2[B_GR * 1280];
__device__ float g_o1[B_GR * D_DIM];
__device__ float g_o2[B_GR * D_DIM];
__device__ float g_fus[B_GR * 6];
__device__ int g_ptr1[T_TOT + 1];
__device__ int g_ptr2[T_TOT + 1];
__device__ int2 g_pack1[E_TOT];
__device__ int2 g_pack2[E_TOT];
__device__ int g_is64[2];

// ---- index dtype detection (parallel): int64 LE => odd 32-bit words all zero ----
__global__ void detect_kernel(const unsigned* e1, const unsigned* e2) {
    __shared__ int ok[2];
    int t = threadIdx.x;
    if (t < 2) ok[t] = 1;
    __syncthreads();
    if (e1[2 * t + 1]) ok[0] = 0;   // benign race: all writers store 0
    if (e2[2 * t + 1]) ok[1] = 0;
    __syncthreads();
    if (t < 2) g_is64[t] = ok[t];
}

__device__ __forceinline__ int loadIdx(const void* p, int is64, long long i) {
    return is64 ? (int)((const long long*)p)[i] : ((const int*)p)[i];
}

// ---- per-graph CSR, dst-grouped, stable order (deterministic sums) ----
__global__ void build_csr(const void* __restrict__ eidx, int which,
                          int* __restrict__ ptr, int2* __restrict__ pack) {
    __shared__ int sl[E_PG], dl[E_PG], cnt[N_PG], base[N_PG];
    int g = blockIdx.x, t = threadIdx.x;
    int is64 = g_is64[which];
    if (t < N_PG) cnt[t] = 0;
    __syncthreads();
    for (int e = t; e < E_PG; e += blockDim.x) {
        long long ge = (long long)g * E_PG + e;
        sl[e] = loadIdx(eidx, is64, ge) - g * N_PG;
        int d = loadIdx(eidx, is64, (long long)E_TOT + ge) - g * N_PG;
        dl[e] = d;
        atomicAdd(&cnt[d], 1);
    }
    __syncthreads();
    if (t == 0) {
        int run = 0;
        for (int n = 0; n < N_PG; n++) {
            base[n] = run;
            ptr[g * N_PG + n] = g * E_PG + run;
            run += cnt[n];
        }
        if (g == 0) ptr[T_TOT] = E_TOT;
    }
    __syncthreads();
    if (t < N_PG) {
        int p = g * E_PG + base[t];
        for (int e = 0; e < E_PG; e++)
            if (dl[e] == t) { pack[p] = make_int2((g * E_PG + e) * D_DIM, sl[e] * D_DIM); p++; }
    }
}

// ---- tf32 conversion (round-to-nearest) ----
__device__ __forceinline__ unsigned to_tf32(float f) {
    unsigned u;
    asm("cvt.rna.tf32.f32 %0, %1;" : "=r"(u) : "f"(f));
    return u;
}

// ---- tensor-core GEMM: C = act(A[M,K] @ B[K,N] + bias) via tf32 mma ----
// CTA tile 128x128, BK=16, 8 warps (4 in M x 2 in N), warp tile 32x64.
// ACT: 0=none, 2=rrelu. OutT: float or __half.
template <int ACT, typename OutT>
__global__ void __launch_bounds__(256) tgemm(const float* __restrict__ A,
                                             const float* __restrict__ Bm,
                                             const float* __restrict__ bias,
                                             OutT* __restrict__ C,
                                             int M, int N, int K) {
    __shared__ unsigned As[2][16 * 132];
    __shared__ unsigned Bs[2][16 * 132];
    int tid = threadIdx.x;
    int wid = tid >> 5, lane = tid & 31;
    int gid = lane >> 2, tg = lane & 3;
    int row0 = blockIdx.y * 128, col0 = blockIdx.x * 128;
    int wrow = (wid & 3) * 32, wcol = (wid >> 2) * 64;
    int arow = tid >> 1, ak = (tid & 1) * 8;
    int bkr = tid >> 5, bcol = (tid & 31) * 4;
    const float* Ap = A + (size_t)(row0 + arow) * K + ak;
    const float* Bp0 = Bm + (size_t)bkr * N + col0 + bcol;
    const float* Bp1 = Bm + (size_t)(bkr + 8) * N + col0 + bcol;

    float acc[2][8][4];
#pragma unroll
    for (int i = 0; i < 2; i++)
#pragma unroll
        for (int j = 0; j < 8; j++)
#pragma unroll
            for (int q = 0; q < 4; q++) acc[i][j][q] = 0.f;

    // initial fill
    {
        float4 a0 = *(const float4*)Ap;
        float4 a1 = *(const float4*)(Ap + 4);
        float4 b0 = *(const float4*)Bp0;
        float4 b1 = *(const float4*)Bp1;
        As[0][(ak + 0) * 132 + arow] = to_tf32(a0.x);
        As[0][(ak + 1) * 132 + arow] = to_tf32(a0.y);
        As[0][(ak + 2) * 132 + arow] = to_tf32(a0.z);
        As[0][(ak + 3) * 132 + arow] = to_tf32(a0.w);
        As[0][(ak + 4) * 132 + arow] = to_tf32(a1.x);
        As[0][(ak + 5) * 132 + arow] = to_tf32(a1.y);
        As[0][(ak + 6) * 132 + arow] = to_tf32(a1.z);
        As[0][(ak + 7) * 132 + arow] = to_tf32(a1.w);
        Bs[0][bkr * 132 + bcol + 0] = to_tf32(b0.x);
        Bs[0][bkr * 132 + bcol + 1] = to_tf32(b0.y);
        Bs[0][bkr * 132 + bcol + 2] = to_tf32(b0.z);
        Bs[0][bkr * 132 + bcol + 3] = to_tf32(b0.w);
        Bs[0][(bkr + 8) * 132 + bcol + 0] = to_tf32(b1.x);
        Bs[0][(bkr + 8) * 132 + bcol + 1] = to_tf32(b1.y);
        Bs[0][(bkr + 8) * 132 + bcol + 2] = to_tf32(b1.z);
        Bs[0][(bkr + 8) * 132 + bcol + 3] = to_tf32(b1.w);
    }
    __syncthreads();

    int NT = K >> 4;
    int buf = 0;
    for (int kt = 0; kt < NT; kt++) {
        float4 pa0, pa1, pb0, pb1;
        if (kt + 1 < NT) {
            pa0 = *(const float4*)(Ap + (kt + 1) * 16);
            pa1 = *(const float4*)(Ap + (kt + 1) * 16 + 4);
            pb0 = *(const float4*)(Bp0 + (size_t)(kt + 1) * 16 * N);
            pb1 = *(const float4*)(Bp1 + (size_t)(kt + 1) * 16 * N);
        }
        const unsigned* as = As[buf];
        const unsigned* bs = Bs[buf];
#pragma unroll
        for (int ks = 0; ks < 2; ks++) {
            int k0 = ks * 8;
            unsigned a[2][4], b[8][2];
#pragma unroll
            for (int i = 0; i < 2; i++) {
                int rb = wrow + i * 16 + gid;
                a[i][0] = as[(k0 + tg) * 132 + rb];
                a[i][1] = as[(k0 + tg) * 132 + rb + 8];
                a[i][2] = as[(k0 + tg + 4) * 132 + rb];
                a[i][3] = as[(k0 + tg + 4) * 132 + rb + 8];
            }
#pragma unroll
            for (int j = 0; j < 8; j++) {
                int cb = wcol + j * 8 + gid;
                b[j][0] = bs[(k0 + tg) * 132 + cb];
                b[j][1] = bs[(k0 + tg + 4) * 132 + cb];
            }
#pragma unroll
            for (int i = 0; i < 2; i++)
#pragma unroll
                for (int j = 0; j < 8; j++) {
                    asm volatile(
                        "mma.sync.aligned.m16n8k8.row.col.f32.tf32.tf32.f32 "
                        "{%0,%1,%2,%3},{%4,%5,%6,%7},{%8,%9},{%0,%1,%2,%3};"
                        : "+f"(acc[i][j][0]), "+f"(acc[i][j][1]),
                          "+f"(acc[i][j][2]), "+f"(acc[i][j][3])
                        : "r"(a[i][0]), "r"(a[i][1]), "r"(a[i][2]), "r"(a[i][3]),
                          "r"(b[j][0]), "r"(b[j][1]));
                }
        }
        if (kt + 1 < NT) {
            buf ^= 1;
            As[buf][(ak + 0) * 132 + arow] = to_tf32(pa0.x);
            As[buf][(ak + 1) * 132 + arow] = to_tf32(pa0.y);
            As[buf][(ak + 2) * 132 + arow] = to_tf32(pa0.z);
            As[buf][(ak + 3) * 132 + arow] = to_tf32(pa0.w);
            As[buf][(ak + 4) * 132 + arow] = to_tf32(pa1.x);
            As[buf][(ak + 5) * 132 + arow] = to_tf32(pa1.y);
            As[buf][(ak + 6) * 132 + arow] = to_tf32(pa1.z);
            As[buf][(ak + 7) * 132 + arow] = to_tf32(pa1.w);
            Bs[buf][bkr * 132 + bcol + 0] = to_tf32(pb0.x);
            Bs[buf][bkr * 132 + bcol + 1] = to_tf32(pb0.y);
            Bs[buf][bkr * 132 + bcol + 2] = to_tf32(pb0.z);
            Bs[buf][bkr * 132 + bcol + 3] = to_tf32(pb0.w);
            Bs[buf][(bkr + 8) * 132 + bcol + 0] = to_tf32(pb1.x);
            Bs[buf][(bkr + 8) * 132 + bcol + 1] = to_tf32(pb1.y);
            Bs[buf][(bkr + 8) * 132 + bcol + 2] = to_tf32(pb1.z);
            Bs[buf][(bkr + 8) * 132 + bcol + 3] = to_tf32(pb1.w);
            __syncthreads();
        }
    }

    // epilogue
#pragma unroll
    for (int j = 0; j < 8; j++) {
        int c = col0 + wcol + j * 8 + tg * 2;
        float b0v = 0.f, b1v = 0.f;
        if (bias) { float2 bb = *(const float2*)(bias + c); b0v = bb.x; b1v = bb.y; }
#pragma unroll
        for (int i = 0; i < 2; i++) {
            int ra = row0 + wrow + i * 16 + gid;
            float v0 = acc[i][j][0] + b0v, v1 = acc[i][j][1] + b1v;
            float v2 = acc[i][j][2] + b0v, v3 = acc[i][j][3] + b1v;
            if (ACT == 2) {
                v0 = v0 >= 0.f ? v0 : SLOPE * v0; v1 = v1 >= 0.f ? v1 : SLOPE * v1;
                v2 = v2 >= 0.f ? v2 : SLOPE * v2; v3 = v3 >= 0.f ? v3 : SLOPE * v3;
            }
            if constexpr (sizeof(OutT) == 2) {
                *(__half2*)((__half*)C + (size_t)ra * N + c) = __floats2half2_rn(v0, v1);
                *(__half2*)((__half*)C + (size_t)(ra + 8) * N + c) = __floats2half2_rn(v2, v3);
            } else {
                *(float2*)((float*)C + (size_t)ra * N + c) = make_float2(v0, v1);
                *(float2*)((float*)C + (size_t)(ra + 8) * N + c) = make_float2(v2, v3);
            }
        }
    }
}

// ---- conv: xo = relu(z + segsum(relu(y[src]+eb)) + bs), one CTA/graph ----
__global__ void conv_kernel(const float* __restrict__ y, const float* __restrict__ z,
                            const __half* __restrict__ eb, const int* __restrict__ ptr,
                            const int2* __restrict__ pack, const float* __restrict__ bs,
                            float* __restrict__ xo) {
    extern __shared__ float ys[];
    int g = blockIdx.x, t = threadIdx.x;
    const float* yg = y + (size_t)g * N_PG * D_DIM;
    for (int i = t; i < N_PG * D_DIM; i += 256) ys[i] = yg[i];
    __syncthreads();
    int q = t >> 6, dd = (t & 63) * 4;
    float4 bsv = *(const float4*)(bs + dd);
    for (int n = q; n < N_PG; n += 4) {
        int p0 = ptr[g * N_PG + n], p1 = ptr[g * N_PG + n + 1];
        float ax = 0.f, ay = 0.f, az = 0.f, aw = 0.f;
        for (int j = p0; j < p1; j++) {
            int2 pr = pack[j];
            float4 yv = *(const float4*)(ys + pr.y + dd);
            uint2 raw = *(const uint2*)(eb + (size_t)pr.x + dd);
            float2 e0 = __half22float2(*(__half2*)&raw.x);
            float2 e1 = __half22float2(*(__half2*)&raw.y);
            ax += fmaxf(yv.x + e0.x, 0.f); ay += fmaxf(yv.y + e0.y, 0.f);
            az += fmaxf(yv.z + e1.x, 0.f); aw += fmaxf(yv.w + e1.y, 0.f);
        }
        size_t o = (size_t)(g * N_PG + n) * D_DIM + dd;
        float4 zv = *(const float4*)(z + o);
        float4 r;
        r.x = fmaxf(zv.x + ax + bsv.x, 0.f); r.y = fmaxf(zv.y + ay + bsv.y, 0.f);
        r.z = fmaxf(zv.z + az + bsv.z, 0.f); r.w = fmaxf(zv.w + aw + bsv.w, 0.f);
        *(float4*)(xo + o) = r;
    }
}

// ---- dot_pool: per-graph 64x64 cross dots, max & mean ----
__global__ void dotpool_kernel(const float* __restrict__ x1, const float* __restrict__ x2,
                               float* __restrict__ fus, int s) {
    extern __shared__ float sm[];
    float* a = sm;
    float* b = sm + 256 * 65;
    __shared__ float rm[256], rs[256];
    int g = blockIdx.x, t = threadIdx.x;
    const float* p1 = x1 + (size_t)g * N_PG * D_DIM;
    const float* p2 = x2 + (size_t)g * N_PG * D_DIM;
    for (int i = t; i < N_PG * D_DIM; i += 256) {
        int n = i >> 8, d = i & 255;
        a[d * 65 + n] = p1[i];
        b[d * 65 + n] = p2[i];
    }
    __syncthreads();
    int ti = t & 15, tj = t >> 4;
    float acc[16];
#pragma unroll
    for (int i = 0; i < 16; i++) acc[i] = 0.f;
    for (int d = 0; d < 256; d++) {
        float av[4], bv[4];
#pragma unroll
        for (int u = 0; u < 4; u++) { av[u] = a[d * 65 + ti + 16 * u]; bv[u] = b[d * 65 + tj + 16 * u]; }
#pragma unroll
        for (int i = 0; i < 4; i++)
#pragma unroll
            for (int j = 0; j < 4; j++) acc[i * 4 + j] += av[i] * bv[j];
    }
    float lmax = -3.4e38f, ls = 0.f;
#pragma unroll
    for (int i = 0; i < 16; i++) { lmax = fmaxf(lmax, acc[i]); ls += acc[i]; }
    rm[t] = lmax; rs[t] = ls;
    __syncthreads();
    for (int o = 128; o > 0; o >>= 1) {
        if (t < o) { rm[t] = fmaxf(rm[t], rm[t + o]); rs[t] += rs[t + o]; }
        __syncthreads();
    }
    if (t == 0) { fus[g * 6 + 2 * s] = rm[0]; fus[g * 6 + 2 * s + 1] = rs[0] / 4096.f; }
}

// ---- readout: [mean, sum, top-3 rows by last feature] -> [B,1280] ----
__global__ void readout_kernel(const float* __restrict__ x, float* __restrict__ r) {
    __shared__ int ord[3];
    int g = blockIdx.x, t = threadIdx.x;
    const float* xg = x + (size_t)g * N_PG * D_DIM;
    float s = 0.f;
    for (int n = 0; n < N_PG; n++) s += xg[n * D_DIM + t];
    r[g * 1280 + t] = s / 64.f;
    r[g * 1280 + 256 + t] = s;
    if (t < 32) {
        float v0 = xg[t * D_DIM + 255], v1 = xg[(t + 32) * D_DIM + 255];
        int i0 = t, i1 = t + 32;
        for (int k = 0; k < 3; k++) {
            float cv; int bi;
            if (v0 > v1 || (v0 == v1 && i0 < i1)) { cv = v0; bi = i0; } else { cv = v1; bi = i1; }
            for (int o = 16; o > 0; o >>= 1) {
                float ov = __shfl_down_sync(0xffffffffu, cv, o);
                int oi = __shfl_down_sync(0xffffffffu, bi, o);
                if (ov > cv || (ov == cv && oi < bi)) { cv = ov; bi = oi; }
            }
            bi = __shfl_sync(0xffffffffu, bi, 0);
            if (t == 0) ord[k] = bi;
            if (bi == i0) v0 = -3.4e38f;
            if (bi == i1) v1 = -3.4e38f;
        }
    }
    __syncthreads();
    for (int k = 0; k < 3; k++) r[g * 1280 + 512 + k * 256 + t] = xg[ord[k] * D_DIM + t];
}

// ---- head: cat[518] @ Wo1 + bo1 -> @ Wo2 + bo2 -> [B,2] ----
__global__ void head_kernel(const float* __restrict__ o1, const float* __restrict__ o2,
                            const float* __restrict__ fus, const float* __restrict__ Wo1,
                            const float* __restrict__ bo1, const float* __restrict__ Wo2,
                            const float* __restrict__ bo2, float* __restrict__ out) {
    __shared__ float cat[518];
    __shared__ float r0[256], r1a[256];
    int g = blockIdx.x, t = threadIdx.x;
    cat[t] = o1[g * 256 + t];
    cat[256 + t] = o2[g * 256 + t];
    if (t < 6) cat[512 + t] = fus[g * 6 + t];
    __syncthreads();
    float h = bo1[t];
    for (int k = 0; k < 518; k++) h += cat[k] * Wo1[k * 256 + t];
    r0[t] = h * Wo2[t * 2];
    r1a[t] = h * Wo2[t * 2 + 1];
    __syncthreads();
    for (int o = 128; o > 0; o >>= 1) {
        if (t < o) { r0[t] += r0[t + o]; r1a[t] += r1a[t + o]; }
        __syncthreads();
    }
    if (t == 0) { out[g * 2] = r0[0] + bo2[0]; out[g * 2 + 1] = r1a[0] + bo2[1]; }
}

extern "C" void kernel_launch(void* const* d_in, const int* in_sizes, int n_in,
                              void* d_out, int out_size) {
    const float* x1 = (const float*)d_in[0];
    const void* ei1 = d_in[1];
    const float* ea1 = (const float*)d_in[2];
    const float* x2 = (const float*)d_in[4];
    const void* ei2 = d_in[5];
    const float* ea2 = (const float*)d_in[6];
    const float* W0_1 = (const float*)d_in[8];  const float* b0_1 = (const float*)d_in[9];
    const float* W0_2 = (const float*)d_in[10]; const float* b0_2 = (const float*)d_in[11];
    const float* Wn1 = (const float*)d_in[12];  const float* We1 = (const float*)d_in[13];
    const float* bm1 = (const float*)d_in[14];  const float* Ws1 = (const float*)d_in[15];
    const float* bs1 = (const float*)d_in[16];
    const float* Wn2 = (const float*)d_in[17];  const float* We2 = (const float*)d_in[18];
    const float* bm2 = (const float*)d_in[19];  const float* Ws2 = (const float*)d_in[20];
    const float* bs2 = (const float*)d_in[21];
    const float* Wf1 = (const float*)d_in[22];  const float* bf1 = (const float*)d_in[23];
    const float* Wf2 = (const float*)d_in[24];  const float* bf2 = (const float*)d_in[25];
    const float* Wo1 = (const float*)d_in[26];  const float* bo1 = (const float*)d_in[27];
    const float* Wo2 = (const float*)d_in[28];  const float* bo2 = (const float*)d_in[29];
    float* out = (float*)d_out;

    void* p;
    cudaGetSymbolAddress(&p, g_eb1);  __half* eb1 = (__half*)p;
    cudaGetSymbolAddress(&p, g_eb2);  __half* eb2 = (__half*)p;
    cudaGetSymbolAddress(&p, g_y);    float* yb = (float*)p;
    cudaGetSymbolAddress(&p, g_z);    float* zb = (float*)p;
    cudaGetSymbolAddress(&p, g_xm1);  float* xm1 = (float*)p;
    cudaGetSymbolAddress(&p, g_xm2);  float* xm2 = (float*)p;
    cudaGetSymbolAddress(&p, g_r1);   float* r1 = (float*)p;
    cudaGetSymbolAddress(&p, g_r2);   float* r2 = (float*)p;
    cudaGetSymbolAddress(&p, g_o1);   float* o1 = (float*)p;
    cudaGetSymbolAddress(&p, g_o2);   float* o2 = (float*)p;
    cudaGetSymbolAddress(&p, g_fus);  float* fus = (float*)p;
    cudaGetSymbolAddress(&p, g_ptr1); int* ptr1 = (int*)p;
    cudaGetSymbolAddress(&p, g_ptr2); int* ptr2 = (int*)p;
    cudaGetSymbolAddress(&p, g_pack1); int2* pack1 = (int2*)p;
    cudaGetSymbolAddress(&p, g_pack2); int2* pack2 = (int2*)p;

    cudaFuncSetAttribute(conv_kernel, cudaFuncAttributeMaxDynamicSharedMemorySize, 65536);
    cudaFuncSetAttribute(dotpool_kernel, cudaFuncAttributeMaxDynamicSharedMemorySize, 2 * 65 * 256 * 4);

    detect_kernel<<<1, 512>>>((const unsigned*)ei1, (const unsigned*)ei2);
    build_csr<<<B_GR, 256>>>(ei1, 0, ptr1, pack1);
    build_csr<<<B_GR, 256>>>(ei2, 1, ptr2, pack2);

    // edge bias as tensor GEMM: eb = ea[E,16] @ We[16,256] + bm  (fp16 out)
    dim3 gE(2, E_TOT / 128);
    tgemm<0, __half><<<gE, 256>>>(ea1, We1, bm1, eb1, E_TOT, 256, 16);
    tgemm<0, __half><<<gE, 256>>>(ea2, We2, bm2, eb2, E_TOT, 256, 16);

    dim3 gT(2, T_TOT / 128);
    tgemm<2, float><<<gT, 256>>>(x1, W0_1, b0_1, xm1, T_TOT, 256, 128);
    tgemm<2, float><<<gT, 256>>>(x2, W0_2, b0_2, xm2, T_TOT, 256, 128);

    for (int s = 0; s < 3; s++) {
        tgemm<0, float><<<gT, 256>>>(xm1, Wn1, nullptr, yb, T_TOT, 256, 256);
        tgemm<0, float><<<gT, 256>>>(xm1, Ws1, nullptr, zb, T_TOT, 256, 256);
        conv_kernel<<<B_GR, 256, 65536>>>(yb, zb, eb1, ptr1, pack1, bs1, xm1);
        tgemm<0, float><<<gT, 256>>>(xm2, Wn2, nullptr, yb, T_TOT, 256, 256);
        tgemm<0, float><<<gT, 256>>>(xm2, Ws2, nullptr, zb, T_TOT, 256, 256);
        conv_kernel<<<B_GR, 256, 65536>>>(yb, zb, eb2, ptr2, pack2, bs2, xm2);
        dotpool_kernel<<<B_GR, 256, 2 * 65 * 256 * 4>>>(xm1, xm2, fus, s);
    }

    readout_kernel<<<B_GR, 256>>>(xm1, r1);
    readout_kernel<<<B_GR, 256>>>(xm2, r2);
    dim3 gF(2, 2);
    tgemm<0, float><<<gF, 256>>>(r1, Wf1, bf1, o1, 256, 256, 1280);
    tgemm<0, float><<<gF, 256>>>(r2, Wf2, bf2, o2, 256, 256, 1280);
    head_kernel<<<B_GR, 256>>>(o1, o2, fus, Wo1, bo1, Wo2, bo2, out);
}

// round 8
// speedup vs baseline: 1.4852x; 1.1740x over previous
#include <cuda_runtime.h>
#include <cuda_fp16.h>
#include <cstdint>
#include <cstddef>

#define B_GR 256
#define N_PG 64
#define D_DIM 256
#define T_TOT 16384
#define E_TOT 524288
#define E_PG 2048
#define BOND_D 16
#define SLOPE 0.22916666666666666f

__device__ __half g_eb1[134217728];   // 256 MB fp16 edge bias mol1
__device__ __half g_eb2[134217728];   // 256 MB fp16 edge bias mol2
__device__ float g_yz[8388608];       // [T][512]: y | z
__device__ float g_xm1[4194304];
__device__ float g_xm2[4194304];
__device__ float g_wcat1[131072];     // [256][512] = Wn1 | Ws1
__device__ float g_wcat2[131072];
__device__ float g_wf1[327680];       // Wf1 with rows 256-511 scaled x64
__device__ float g_wf2[327680];
__device__ float g_r1[B_GR * 1280];
__device__ float g_r2[B_GR * 1280];
__device__ float g_o1[B_GR * D_DIM];
__device__ float g_o2[B_GR * D_DIM];
__device__ float g_fus[B_GR * 6];
__device__ int g_ptr1[T_TOT + 1];
__device__ int g_ptr2[T_TOT + 1];
__device__ int2 g_pack1[E_TOT];
__device__ int2 g_pack2[E_TOT];
__device__ int g_is64[2];

// ---- index dtype detection (parallel): int64 LE => odd 32-bit words all zero ----
__global__ void detect_kernel(const unsigned* e1, const unsigned* e2) {
    __shared__ int ok[2];
    int t = threadIdx.x;
    if (t < 2) ok[t] = 1;
    __syncthreads();
    if (e1[2 * t + 1]) ok[0] = 0;   // benign race: all writers store 0
    if (e2[2 * t + 1]) ok[1] = 0;
    __syncthreads();
    if (t < 2) g_is64[t] = ok[t];
}

__device__ __forceinline__ int loadIdx(const void* p, int is64, long long i) {
    return is64 ? (int)((const long long*)p)[i] : ((const int*)p)[i];
}

// ---- per-graph CSR, dst-grouped, stable order (deterministic sums) ----
__global__ void build_csr(const void* __restrict__ eidx, int which,
                          int* __restrict__ ptr, int2* __restrict__ pack) {
    __shared__ int sl[E_PG], dl[E_PG], cnt[N_PG], base[N_PG];
    int g = blockIdx.x, t = threadIdx.x;
    int is64 = g_is64[which];
    if (t < N_PG) cnt[t] = 0;
    __syncthreads();
    for (int e = t; e < E_PG; e += blockDim.x) {
        long long ge = (long long)g * E_PG + e;
        sl[e] = loadIdx(eidx, is64, ge) - g * N_PG;
        int d = loadIdx(eidx, is64, (long long)E_TOT + ge) - g * N_PG;
        dl[e] = d;
        atomicAdd(&cnt[d], 1);
    }
    __syncthreads();
    if (t == 0) {
        int run = 0;
        for (int n = 0; n < N_PG; n++) {
            base[n] = run;
            ptr[g * N_PG + n] = g * E_PG + run;
            run += cnt[n];
        }
        if (g == 0) ptr[T_TOT] = E_TOT;
    }
    __syncthreads();
    if (t < N_PG) {
        int p = g * E_PG + base[t];
        for (int e = 0; e < E_PG; e++)
            if (dl[e] == t) { pack[p] = make_int2((g * E_PG + e) * D_DIM, sl[e] * D_DIM); p++; }
    }
}

// ---- weight concat: Wcat[k][0:256]=Wn[k], [256:512]=Ws[k] ----
__global__ void pack2_kernel(const float* __restrict__ Wn, const float* __restrict__ Ws,
                             float* __restrict__ Wcat) {
    int k = blockIdx.x, t = threadIdx.x;
    Wcat[k * 512 + t] = Wn[k * 256 + t];
    Wcat[k * 512 + 256 + t] = Ws[k * 256 + t];
}

// ---- Wf pack: rows 256-511 scaled x64 (sum channel fed as mean) ----
__global__ void packwf_kernel(const float* __restrict__ Wf, float* __restrict__ dst) {
    int k = blockIdx.x, t = threadIdx.x;
    float sc = (k >= 256 && k < 512) ? 64.f : 1.f;
    dst[k * 256 + t] = Wf[k * 256 + t] * sc;
}

// ---- helpers ----
__device__ __forceinline__ uint32_t su32(const void* p) {
    return (uint32_t)__cvta_generic_to_shared(p);
}
__device__ __forceinline__ void ldsm4(uint32_t* r, uint32_t addr) {
    asm volatile("ldmatrix.sync.aligned.m8n8.x4.shared.b16 {%0,%1,%2,%3}, [%4];"
                 : "=r"(r[0]), "=r"(r[1]), "=r"(r[2]), "=r"(r[3]) : "r"(addr));
}
__device__ __forceinline__ void ldsm4t(uint32_t* r, uint32_t addr) {
    asm volatile("ldmatrix.sync.aligned.m8n8.x4.trans.shared.b16 {%0,%1,%2,%3}, [%4];"
                 : "=r"(r[0]), "=r"(r[1]), "=r"(r[2]), "=r"(r[3]) : "r"(addr));
}
__device__ __forceinline__ void mma16816(float* c, const uint32_t* a, uint32_t b0, uint32_t b1) {
    asm volatile(
        "mma.sync.aligned.m16n8k16.row.col.f32.f16.f16.f32 "
        "{%0,%1,%2,%3},{%4,%5,%6,%7},{%8,%9},{%0,%1,%2,%3};"
        : "+f"(c[0]), "+f"(c[1]), "+f"(c[2]), "+f"(c[3])
        : "r"(a[0]), "r"(a[1]), "r"(a[2]), "r"(a[3]), "r"(b0), "r"(b1));
}

#define A_PAD 24   // halves per A row (16 data + 8 pad)
#define B_PAD 136  // halves per B row (128 data + 8 pad)

__device__ __forceinline__ void fill_tiles(__half* as_, __half* bs_,
                                           float4 a0, float4 a1, float4 b0, float4 b1,
                                           int arow, int ak, int bkr, int bcol) {
    __half2 h0 = __floats2half2_rn(a0.x, a0.y), h1 = __floats2half2_rn(a0.z, a0.w);
    __half2 h2 = __floats2half2_rn(a1.x, a1.y), h3 = __floats2half2_rn(a1.z, a1.w);
    uint4 u;
    u.x = *(uint32_t*)&h0; u.y = *(uint32_t*)&h1; u.z = *(uint32_t*)&h2; u.w = *(uint32_t*)&h3;
    *(uint4*)&as_[arow * A_PAD + ak] = u;
    __half2 p0 = __floats2half2_rn(b0.x, b0.y), p1 = __floats2half2_rn(b0.z, b0.w);
    uint2 v; v.x = *(uint32_t*)&p0; v.y = *(uint32_t*)&p1;
    *(uint2*)&bs_[bkr * B_PAD + bcol] = v;
    p0 = __floats2half2_rn(b1.x, b1.y); p1 = __floats2half2_rn(b1.z, b1.w);
    v.x = *(uint32_t*)&p0; v.y = *(uint32_t*)&p1;
    *(uint2*)&bs_[(bkr + 8) * B_PAD + bcol] = v;
}

// ---- fp16 tensor-core GEMM: C = act(A[M,K]@B[K,N] + bias), fp32 accum ----
// CTA tile 128x128, BK=16, 8 warps (4M x 2N), warp tile 32x64, double-buffered,
// ldmatrix fragment loads. ACT: 0=none, 2=rrelu.
template <int ACT, typename OutT>
__global__ void __launch_bounds__(256) hgemm(const float* __restrict__ A,
                                             const float* __restrict__ Bm,
                                             const float* __restrict__ bias,
                                             OutT* __restrict__ C,
                                             int M, int N, int K) {
    __shared__ __align__(16) __half As[2][128 * A_PAD];
    __shared__ __align__(16) __half Bs[2][16 * B_PAD];
    int tid = threadIdx.x;
    int wid = tid >> 5, lane = tid & 31;
    int gid = lane >> 2, tg = lane & 3;
    int row0 = blockIdx.y * 128, col0 = blockIdx.x * 128;
    int wrow = (wid & 3) * 32, wcol = (wid >> 2) * 64;
    int arow = tid >> 1, ak = (tid & 1) * 8;
    int bkr = tid >> 5, bcol = (tid & 31) * 4;
    const float* Ap = A + (size_t)(row0 + arow) * K + ak;
    const float* Bp0 = Bm + (size_t)bkr * N + col0 + bcol;
    const float* Bp1 = Bm + (size_t)(bkr + 8) * N + col0 + bcol;

    // ldmatrix source addresses
    uint32_t aad[2][2], bad[2];
    {
        int arw = (lane & 15), acl = (lane >> 4) * 8;
        int bk = (lane & 7) + ((lane >> 4) & 1) * 8;
        int bn = wcol + ((lane >> 3) & 1) * 8;
#pragma unroll
        for (int b = 0; b < 2; b++) {
            aad[b][0] = su32(&As[b][(wrow + arw) * A_PAD + acl]);
            aad[b][1] = su32(&As[b][(wrow + 16 + arw) * A_PAD + acl]);
            bad[b] = su32(&Bs[b][bk * B_PAD + bn]);
        }
    }

    float acc[2][8][4];
#pragma unroll
    for (int i = 0; i < 2; i++)
#pragma unroll
        for (int j = 0; j < 8; j++)
#pragma unroll
            for (int q = 0; q < 4; q++) acc[i][j][q] = 0.f;

    {
        float4 a0 = *(const float4*)Ap;
        float4 a1 = *(const float4*)(Ap + 4);
        float4 b0 = *(const float4*)Bp0;
        float4 b1 = *(const float4*)Bp1;
        fill_tiles(As[0], Bs[0], a0, a1, b0, b1, arow, ak, bkr, bcol);
    }
    __syncthreads();

    int NT = K >> 4;
    int buf = 0;
    for (int kt = 0; kt < NT; kt++) {
        float4 pa0, pa1, pb0, pb1;
        if (kt + 1 < NT) {
            pa0 = *(const float4*)(Ap + (kt + 1) * 16);
            pa1 = *(const float4*)(Ap + (kt + 1) * 16 + 4);
            pb0 = *(const float4*)(Bp0 + (size_t)(kt + 1) * 16 * N);
            pb1 = *(const float4*)(Bp1 + (size_t)(kt + 1) * 16 * N);
        }
        uint32_t a[2][4], bf[4][4];
        ldsm4(a[0], aad[buf][0]);
        ldsm4(a[1], aad[buf][1]);
#pragma unroll
        for (int jp = 0; jp < 4; jp++) ldsm4t(bf[jp], bad[buf] + jp * 32);
#pragma unroll
        for (int i = 0; i < 2; i++)
#pragma unroll
            for (int j = 0; j < 8; j++)
                mma16816(acc[i][j], a[i], bf[j >> 1][j & 1], bf[j >> 1][2 + (j & 1)]);
        if (kt + 1 < NT) {
            buf ^= 1;
            fill_tiles(As[buf], Bs[buf], pa0, pa1, pb0, pb1, arow, ak, bkr, bcol);
            __syncthreads();
        }
    }

    // epilogue: acc[i][j]: rows gid/gid+8 of tile i, cols j*8 + tg*2, +1
#pragma unroll
    for (int j = 0; j < 8; j++) {
        int c = col0 + wcol + j * 8 + tg * 2;
        float b0v = 0.f, b1v = 0.f;
        if (bias) { float2 bb = *(const float2*)(bias + c); b0v = bb.x; b1v = bb.y; }
#pragma unroll
        for (int i = 0; i < 2; i++) {
            int ra = row0 + wrow + i * 16 + gid;
            float v0 = acc[i][j][0] + b0v, v1 = acc[i][j][1] + b1v;
            float v2 = acc[i][j][2] + b0v, v3 = acc[i][j][3] + b1v;
            if (ACT == 2) {
                v0 = v0 >= 0.f ? v0 : SLOPE * v0; v1 = v1 >= 0.f ? v1 : SLOPE * v1;
                v2 = v2 >= 0.f ? v2 : SLOPE * v2; v3 = v3 >= 0.f ? v3 : SLOPE * v3;
            }
            if constexpr (sizeof(OutT) == 2) {
                *(__half2*)((__half*)C + (size_t)ra * N + c) = __floats2half2_rn(v0, v1);
                *(__half2*)((__half*)C + (size_t)(ra + 8) * N + c) = __floats2half2_rn(v2, v3);
            } else {
                *(float2*)((float*)C + (size_t)ra * N + c) = make_float2(v0, v1);
                *(float2*)((float*)C + (size_t)(ra + 8) * N + c) = make_float2(v2, v3);
            }
        }
    }
}

// ---- conv: xo = relu(z + segsum(relu(y[src]+eb)) + bs), one CTA/graph ----
// yz: [T][512], cols 0:256 = y, 256:512 = z
__global__ void conv_kernel(const float* __restrict__ yz,
                            const __half* __restrict__ eb, const int* __restrict__ ptr,
                            const int2* __restrict__ pack, const float* __restrict__ bs,
                            float* __restrict__ xo) {
    extern __shared__ float ys[];
    int g = blockIdx.x, t = threadIdx.x;
    const float* yg = yz + (size_t)g * N_PG * 512;
    for (int i = t; i < N_PG * D_DIM; i += 256) {
        int n = i >> 8, d = i & 255;
        ys[i] = yg[n * 512 + d];
    }
    __syncthreads();
    int q = t >> 6, dd = (t & 63) * 4;
    float4 bsv = *(const float4*)(bs + dd);
    for (int n = q; n < N_PG; n += 4) {
        int p0 = ptr[g * N_PG + n], p1 = ptr[g * N_PG + n + 1];
        float ax = 0.f, ay = 0.f, az = 0.f, aw = 0.f;
#pragma unroll 2
        for (int j = p0; j < p1; j++) {
            int2 pr = pack[j];
            float4 yv = *(const float4*)(ys + pr.y + dd);
            uint2 raw = *(const uint2*)(eb + (size_t)pr.x + dd);
            float2 e0 = __half22float2(*(__half2*)&raw.x);
            float2 e1 = __half22float2(*(__half2*)&raw.y);
            ax += fmaxf(yv.x + e0.x, 0.f); ay += fmaxf(yv.y + e0.y, 0.f);
            az += fmaxf(yv.z + e1.x, 0.f); aw += fmaxf(yv.w + e1.y, 0.f);
        }
        float4 zv = *(const float4*)(yg + n * 512 + 256 + dd);
        size_t o = (size_t)(g * N_PG + n) * D_DIM + dd;
        float4 r;
        r.x = fmaxf(zv.x + ax + bsv.x, 0.f); r.y = fmaxf(zv.y + ay + bsv.y, 0.f);
        r.z = fmaxf(zv.z + az + bsv.z, 0.f); r.w = fmaxf(zv.w + aw + bsv.w, 0.f);
        *(float4*)(xo + o) = r;
    }
}

// ---- dot_pool: per-graph 64x64 cross dots, max & mean ----
__global__ void dotpool_kernel(const float* __restrict__ x1, const float* __restrict__ x2,
                               float* __restrict__ fus, int s) {
    extern __shared__ float sm[];
    float* a = sm;
    float* b = sm + 256 * 65;
    __shared__ float rm[256], rs[256];
    int g = blockIdx.x, t = threadIdx.x;
    const float* p1 = x1 + (size_t)g * N_PG * D_DIM;
    const float* p2 = x2 + (size_t)g * N_PG * D_DIM;
    for (int i = t; i < N_PG * D_DIM; i += 256) {
        int n = i >> 8, d = i & 255;
        a[d * 65 + n] = p1[i];
        b[d * 65 + n] = p2[i];
    }
    __syncthreads();
    int ti = t & 15, tj = t >> 4;
    float acc[16];
#pragma unroll
    for (int i = 0; i < 16; i++) acc[i] = 0.f;
    for (int d = 0; d < 256; d++) {
        float av[4], bv[4];
#pragma unroll
        for (int u = 0; u < 4; u++) { av[u] = a[d * 65 + ti + 16 * u]; bv[u] = b[d * 65 + tj + 16 * u]; }
#pragma unroll
        for (int i = 0; i < 4; i++)
#pragma unroll
            for (int j = 0; j < 4; j++) acc[i * 4 + j] += av[i] * bv[j];
    }
    float lmax = -3.4e38f, ls = 0.f;
#pragma unroll
    for (int i = 0; i < 16; i++) { lmax = fmaxf(lmax, acc[i]); ls += acc[i]; }
    rm[t] = lmax; rs[t] = ls;
    __syncthreads();
    for (int o = 128; o > 0; o >>= 1) {
        if (t < o) { rm[t] = fmaxf(rm[t], rm[t + o]); rs[t] += rs[t + o]; }
        __syncthreads();
    }
    if (t == 0) { fus[g * 6 + 2 * s] = rm[0]; fus[g * 6 + 2 * s + 1] = rs[0] / 4096.f; }
}

// ---- readout: [mean, mean(sum ch, pre-scaled Wf), top-3 rows] -> [B,1280] ----
__global__ void readout_kernel(const float* __restrict__ x, float* __restrict__ r) {
    __shared__ int ord[3];
    int g = blockIdx.x, t = threadIdx.x;
    const float* xg = x + (size_t)g * N_PG * D_DIM;
    float s = 0.f;
    for (int n = 0; n < N_PG; n++) s += xg[n * D_DIM + t];
    r[g * 1280 + t] = s / 64.f;
    r[g * 1280 + 256 + t] = s / 64.f;   // sum channel stored as mean; Wf rows x64
    if (t < 32) {
        float v0 = xg[t * D_DIM + 255], v1 = xg[(t + 32) * D_DIM + 255];
        int i0 = t, i1 = t + 32;
        for (int k = 0; k < 3; k++) {
            float cv; int bi;
            if (v0 > v1 || (v0 == v1 && i0 < i1)) { cv = v0; bi = i0; } else { cv = v1; bi = i1; }
            for (int o = 16; o > 0; o >>= 1) {
                float ov = __shfl_down_sync(0xffffffffu, cv, o);
                int oi = __shfl_down_sync(0xffffffffu, bi, o);
                if (ov > cv || (ov == cv && oi < bi)) { cv = ov; bi = oi; }
            }
            bi = __shfl_sync(0xffffffffu, bi, 0);
            if (t == 0) ord[k] = bi;
            if (bi == i0) v0 = -3.4e38f;
            if (bi == i1) v1 = -3.4e38f;
        }
    }
    __syncthreads();
    for (int k = 0; k < 3; k++) r[g * 1280 + 512 + k * 256 + t] = xg[ord[k] * D_DIM + t];
}

// ---- head: cat[518] @ Wo1 + bo1 -> @ Wo2 + bo2 -> [B,2] ----
__global__ void head_kernel(const float* __restrict__ o1, const float* __restrict__ o2,
                            const float* __restrict__ fus, const float* __restrict__ Wo1,
                            const float* __restrict__ bo1, const float* __restrict__ Wo2,
                            const float* __restrict__ bo2, float* __restrict__ out) {
    __shared__ float cat[518];
    __shared__ float r0[256], r1a[256];
    int g = blockIdx.x, t = threadIdx.x;
    cat[t] = o1[g * 256 + t];
    cat[256 + t] = o2[g * 256 + t];
    if (t < 6) cat[512 + t] = fus[g * 6 + t];
    __syncthreads();
    float h = bo1[t];
    for (int k = 0; k < 518; k++) h += cat[k] * Wo1[k * 256 + t];
    r0[t] = h * Wo2[t * 2];
    r1a[t] = h * Wo2[t * 2 + 1];
    __syncthreads();
    for (int o = 128; o > 0; o >>= 1) {
        if (t < o) { r0[t] += r0[t + o]; r1a[t] += r1a[t + o]; }
        __syncthreads();
    }
    if (t == 0) { out[g * 2] = r0[0] + bo2[0]; out[g * 2 + 1] = r1a[0] + bo2[1]; }
}

extern "C" void kernel_launch(void* const* d_in, const int* in_sizes, int n_in,
                              void* d_out, int out_size) {
    const float* x1 = (const float*)d_in[0];
    const void* ei1 = d_in[1];
    const float* ea1 = (const float*)d_in[2];
    const float* x2 = (const float*)d_in[4];
    const void* ei2 = d_in[5];
    const float* ea2 = (const float*)d_in[6];
    const float* W0_1 = (const float*)d_in[8];  const float* b0_1 = (const float*)d_in[9];
    const float* W0_2 = (const float*)d_in[10]; const float* b0_2 = (const float*)d_in[11];
    const float* Wn1 = (const float*)d_in[12];  const float* We1 = (const float*)d_in[13];
    const float* bm1 = (const float*)d_in[14];  const float* Ws1 = (const float*)d_in[15];
    const float* bs1 = (const float*)d_in[16];
    const float* Wn2 = (const float*)d_in[17];  const float* We2 = (const float*)d_in[18];
    const float* bm2 = (const float*)d_in[19];  const float* Ws2 = (const float*)d_in[20];
    const float* bs2 = (const float*)d_in[21];
    const float* Wf1 = (const float*)d_in[22];  const float* bf1 = (const float*)d_in[23];
    const float* Wf2 = (const float*)d_in[24];  const float* bf2 = (const float*)d_in[25];
    const float* Wo1 = (const float*)d_in[26];  const float* bo1 = (const float*)d_in[27];
    const float* Wo2 = (const float*)d_in[28];  const float* bo2 = (const float*)d_in[29];
    float* out = (float*)d_out;

    void* p;
    cudaGetSymbolAddress(&p, g_eb1);  __half* eb1 = (__half*)p;
    cudaGetSymbolAddress(&p, g_eb2);  __half* eb2 = (__half*)p;
    cudaGetSymbolAddress(&p, g_yz);   float* yz = (float*)p;
    cudaGetSymbolAddress(&p, g_xm1);  float* xm1 = (float*)p;
    cudaGetSymbolAddress(&p, g_xm2);  float* xm2 = (float*)p;
    cudaGetSymbolAddress(&p, g_wcat1); float* wc1 = (float*)p;
    cudaGetSymbolAddress(&p, g_wcat2); float* wc2 = (float*)p;
    cudaGetSymbolAddress(&p, g_wf1);  float* wf1 = (float*)p;
    cudaGetSymbolAddress(&p, g_wf2);  float* wf2 = (float*)p;
    cudaGetSymbolAddress(&p, g_r1);   float* r1 = (float*)p;
    cudaGetSymbolAddress(&p, g_r2);   float* r2 = (float*)p;
    cudaGetSymbolAddress(&p, g_o1);   float* o1 = (float*)p;
    cudaGetSymbolAddress(&p, g_o2);   float* o2 = (float*)p;
    cudaGetSymbolAddress(&p, g_fus);  float* fus = (float*)p;
    cudaGetSymbolAddress(&p, g_ptr1); int* ptr1 = (int*)p;
    cudaGetSymbolAddress(&p, g_ptr2); int* ptr2 = (int*)p;
    cudaGetSymbolAddress(&p, g_pack1); int2* pack1 = (int2*)p;
    cudaGetSymbolAddress(&p, g_pack2); int2* pack2 = (int2*)p;

    cudaFuncSetAttribute(conv_kernel, cudaFuncAttributeMaxDynamicSharedMemorySize, 65536);
    cudaFuncSetAttribute(dotpool_kernel, cudaFuncAttributeMaxDynamicSharedMemorySize, 2 * 65 * 256 * 4);

    detect_kernel<<<1, 512>>>((const unsigned*)ei1, (const unsigned*)ei2);
    build_csr<<<B_GR, 256>>>(ei1, 0, ptr1, pack1);
    build_csr<<<B_GR, 256>>>(ei2, 1, ptr2, pack2);
    pack2_kernel<<<256, 256>>>(Wn1, Ws1, wc1);
    pack2_kernel<<<256, 256>>>(Wn2, Ws2, wc2);
    packwf_kernel<<<1280, 256>>>(Wf1, wf1);
    packwf_kernel<<<1280, 256>>>(Wf2, wf2);

    // edge bias: eb = ea[E,16] @ We[16,256] + bm  (fp16 out)
    dim3 gE(2, E_TOT / 128);
    hgemm<0, __half><<<gE, 256>>>(ea1, We1, bm1, eb1, E_TOT, 256, 16);
    hgemm<0, __half><<<gE, 256>>>(ea2, We2, bm2, eb2, E_TOT, 256, 16);

    dim3 gT(2, T_TOT / 128);
    hgemm<2, float><<<gT, 256>>>(x1, W0_1, b0_1, xm1, T_TOT, 256, 128);
    hgemm<2, float><<<gT, 256>>>(x2, W0_2, b0_2, xm2, T_TOT, 256, 128);

    dim3 gYZ(4, T_TOT / 128);   // N=512
    for (int s = 0; s < 3; s++) {
        hgemm<0, float><<<gYZ, 256>>>(xm1, wc1, nullptr, yz, T_TOT, 512, 256);
        conv_kernel<<<B_GR, 256, 65536>>>(yz, eb1, ptr1, pack1, bs1, xm1);
        hgemm<0, float><<<gYZ, 256>>>(xm2, wc2, nullptr, yz, T_TOT, 512, 256);
        conv_kernel<<<B_GR, 256, 65536>>>(yz, eb2, ptr2, pack2, bs2, xm2);
        dotpool_kernel<<<B_GR, 256, 2 * 65 * 256 * 4>>>(xm1, xm2, fus, s);
    }

    readout_kernel<<<B_GR, 256>>>(xm1, r1);
    readout_kernel<<<B_GR, 256>>>(xm2, r2);
    dim3 gF(2, 2);
    hgemm<0, float><<<gF, 256>>>(r1, wf1, bf1, o1, 256, 256, 1280);
    hgemm<0, float><<<gF, 256>>>(r2, wf2, bf2, o2, 256, 256, 1280);
    head_kernel<<<B_GR, 256>>>(o1, o2, fus, Wo1, bo1, Wo2, bo2, out);
}